// round 9
// baseline (speedup 1.0000x reference)
#include <cuda_runtime.h>
#include <math.h>

// ---------------------------------------------------------------------------
// TensoRF shading: softplus density -> alpha -> transmittance weights,
// per-sample MLP (390 -> 128 -> 128 -> 3, relu/relu/sigmoid),
// rgb_map[r] = sum_s weights[r,s] * rgb[r,s].
//
// Kernel 1 (mlp_kernel): per 16-sample tile, build PE input in SMEM, run the
// MLP fp32 register-tiled (thread = 4 features x 4 samples), write rgb to a
// static device scratch buffer.
// Kernel 2 (reduce_kernel): thread-per-ray sequential composite.
// ---------------------------------------------------------------------------

#define NRAYS 4096
#define NS    128
#define NSAMP (NRAYS * NS)
#define APPD  27
#define INC   390
#define FC    128
#define STILE 16

static __device__ float g_rgb[(size_t)NSAMP * 3];

__global__ void __launch_bounds__(128) mlp_kernel(
    const float* __restrict__ app,
    const float* __restrict__ view,
    const float* __restrict__ W1, const float* __restrict__ b1,
    const float* __restrict__ W2, const float* __restrict__ b2,
    const float* __restrict__ W3, const float* __restrict__ b3)
{
    __shared__ __align__(16) float x_sm[STILE][392];   // encoded input (390 used)
    __shared__ __align__(16) float h_sm[STILE][FC];    // hidden 1
    __shared__ __align__(16) float h2_sm[STILE][132];  // hidden 2 (padded stride)
    __shared__ float w3_sm[FC * 3];
    __shared__ float b3_sm[3];

    const int tid = threadIdx.x;
    const size_t base = (size_t)blockIdx.x * STILE;

    // ---- stage W3 / b3 to shared (avoids 200M uncoalesced LDGs in layer 3) ----
    w3_sm[tid]       = W3[tid];
    w3_sm[tid + 128] = W3[tid + 128];
    w3_sm[tid + 256] = W3[tid + 256];
    if (tid < 3) b3_sm[tid] = b3[tid];

    // ---- build encoded input tile: [feat(27) | view(3) | sin(PE feat)(162)
    //      | cos(PE feat)(162) | sin(PE view)(18) | cos(PE view)(18)] ----
    {
        const int s = tid >> 3;   // 0..15 sample in tile
        const int j = tid & 7;    // 8 threads per sample
        const size_t gs = base + s;
        const float* af = app + gs * APPD;
        for (int c = j; c < APPD; c += 8) {
            float v = af[c];
            x_sm[s][c] = v;
            float p = v;
            #pragma unroll
            for (int f = 0; f < 6; f++) {
                float sn, cs;
                __sincosf(p, &sn, &cs);
                x_sm[s][30  + c * 6 + f] = sn;
                x_sm[s][192 + c * 6 + f] = cs;
                p += p;   // * 2^f
            }
        }
        if (j < 3) {
            float v = view[gs * 3 + j];
            x_sm[s][27 + j] = v;
            float p = v;
            #pragma unroll
            for (int f = 0; f < 6; f++) {
                float sn, cs;
                __sincosf(p, &sn, &cs);
                x_sm[s][354 + j * 6 + f] = sn;
                x_sm[s][372 + j * 6 + f] = cs;
                p += p;
            }
        }
    }
    __syncthreads();

    const int fg = tid & 31;   // feature group: output features 4*fg .. 4*fg+3
    const int sg = tid >> 5;   // sample group : samples 4*sg .. 4*sg+3
    const int s0 = sg * 4;

    float4 acc[4];

    // ---- layer 1: [16,390] x [390,128], W1 streamed from L2 ----
    #pragma unroll
    for (int i = 0; i < 4; i++) acc[i] = make_float4(0.f, 0.f, 0.f, 0.f);
    {
        const float4* w1p = (const float4*)(W1 + 4 * fg);
        #pragma unroll 4
        for (int c = 0; c < INC; c++) {
            float4 w = w1p[c * 32];
            #pragma unroll
            for (int si = 0; si < 4; si++) {
                float x = x_sm[s0 + si][c];
                acc[si].x = fmaf(x, w.x, acc[si].x);
                acc[si].y = fmaf(x, w.y, acc[si].y);
                acc[si].z = fmaf(x, w.z, acc[si].z);
                acc[si].w = fmaf(x, w.w, acc[si].w);
            }
        }
        float4 bb = *(const float4*)(b1 + 4 * fg);
        #pragma unroll
        for (int si = 0; si < 4; si++) {
            float4 h;
            h.x = fmaxf(acc[si].x + bb.x, 0.f);
            h.y = fmaxf(acc[si].y + bb.y, 0.f);
            h.z = fmaxf(acc[si].z + bb.z, 0.f);
            h.w = fmaxf(acc[si].w + bb.w, 0.f);
            *(float4*)&h_sm[s0 + si][4 * fg] = h;
        }
    }
    __syncthreads();

    // ---- layer 2: [16,128] x [128,128] ----
    #pragma unroll
    for (int i = 0; i < 4; i++) acc[i] = make_float4(0.f, 0.f, 0.f, 0.f);
    {
        const float4* w2p = (const float4*)(W2 + 4 * fg);
        #pragma unroll 4
        for (int c = 0; c < FC; c++) {
            float4 w = w2p[c * 32];
            #pragma unroll
            for (int si = 0; si < 4; si++) {
                float x = h_sm[s0 + si][c];
                acc[si].x = fmaf(x, w.x, acc[si].x);
                acc[si].y = fmaf(x, w.y, acc[si].y);
                acc[si].z = fmaf(x, w.z, acc[si].z);
                acc[si].w = fmaf(x, w.w, acc[si].w);
            }
        }
        float4 bb = *(const float4*)(b2 + 4 * fg);
        #pragma unroll
        for (int si = 0; si < 4; si++) {
            float4 h;
            h.x = fmaxf(acc[si].x + bb.x, 0.f);
            h.y = fmaxf(acc[si].y + bb.y, 0.f);
            h.z = fmaxf(acc[si].z + bb.z, 0.f);
            h.w = fmaxf(acc[si].w + bb.w, 0.f);
            *(float4*)&h2_sm[s0 + si][4 * fg] = h;
        }
    }
    __syncthreads();

    // ---- layer 3: [16,128] x [128,3] + sigmoid ----
    if (tid < 48) {
        const int s = tid / 3;
        const int o = tid - 3 * s;
        float sum = b3_sm[o];
        #pragma unroll 8
        for (int g = 0; g < FC; g++)
            sum = fmaf(h2_sm[s][g], w3_sm[g * 3 + o], sum);
        float r = 1.0f / (1.0f + expf(-sum));
        g_rgb[(base + s) * 3 + o] = r;
    }
}

// ---------------------------------------------------------------------------
// Per-ray composite: alpha = 1 - exp(-softplus(sf - 10) * d * 25),
// last alpha forced to 1; w_i = alpha_i * prod_{j<i}(1 - alpha_j + 1e-10).
// ---------------------------------------------------------------------------
__global__ void __launch_bounds__(128) reduce_kernel(
    const float* __restrict__ sf,
    const float* __restrict__ dd,
    float* __restrict__ out)
{
    const int r = blockIdx.x * blockDim.x + threadIdx.x;
    if (r >= NRAYS) return;

    const float* s  = sf + (size_t)r * NS;
    const float* d  = dd + (size_t)r * NS;
    const float* rb = g_rgb + (size_t)r * NS * 3;

    float T = 1.0f, o0 = 0.0f, o1 = 0.0f, o2 = 0.0f;
    #pragma unroll 4
    for (int i = 0; i < NS; i++) {
        float x = s[i] - 10.0f;                     // density shift
        float sig = log1pf(expf(x));                // softplus
        float alpha = (i == NS - 1) ? 1.0f
                    : (1.0f - expf(-sig * d[i] * 25.0f));
        float w = alpha * T;                        // T = prod_{j<i}(...)
        o0 = fmaf(w, rb[i * 3 + 0], o0);
        o1 = fmaf(w, rb[i * 3 + 1], o1);
        o2 = fmaf(w, rb[i * 3 + 2], o2);
        T *= (1.0f - alpha + 1e-10f);
    }
    out[r * 3 + 0] = o0;
    out[r * 3 + 1] = o1;
    out[r * 3 + 2] = o2;
}

// ---------------------------------------------------------------------------
extern "C" void kernel_launch(void* const* d_in, const int* in_sizes, int n_in,
                              void* d_out, int out_size)
{
    const float* sigma = (const float*)d_in[0];  // [4096,128]
    const float* app   = (const float*)d_in[1];  // [4096,128,27]
    const float* view  = (const float*)d_in[2];  // [4096,128,3]
    const float* dists = (const float*)d_in[3];  // [4096,128]
    const float* W1    = (const float*)d_in[4];  // [390,128]
    const float* b1    = (const float*)d_in[5];  // [128]
    const float* W2    = (const float*)d_in[6];  // [128,128]
    const float* b2    = (const float*)d_in[7];  // [128]
    const float* W3    = (const float*)d_in[8];  // [128,3]
    const float* b3    = (const float*)d_in[9];  // [3]
    float* out = (float*)d_out;                  // [4096,3]

    mlp_kernel<<<NSAMP / STILE, 128>>>(app, view, W1, b1, W2, b2, W3, b3);
    reduce_kernel<<<NRAYS / 128, 128>>>(sigma, dists, out);
}